// round 10
// baseline (speedup 1.0000x reference)
#include <cuda_runtime.h>
#include <math.h>
#include <stdint.h>

// ---------------------------------------------------------------------------
// B=128, T=32, V=64, D=512.  score[128][128].
// sm_100 BASELINE target: mma.sync s8 (m16n8k32) + cp.async + ldmatrix.
// 2-level int8 row-scaled split:  x = s*(q1 + q2/254) + O(s/508)
//   score = sA[r]*sB[c]*( Σq1a*q1b + (Σq1a*q2b + Σq2a*q1b)/254 )
//   quant_prep:  per-row amax+quantize to q1/q2 int8 + scales; softmax weights
//   gemm_kernel: PERSISTENT (296 CTAs, 2/SM), each loops ~14 tiles of
//                128x64; cp.async double-buffer runs continuously across
//                tiles (global chunk counter); fused scale+max epilogue in
//                separate smem scratch overlaps next tile's copies
//   loss_kernel: smem-staged /temp log-softmax diagonals -> scalar
// ---------------------------------------------------------------------------

#define NEG_BIG (-3.0e38f)

__device__ float g_wA[128 * 32];
__device__ float g_wB[128 * 64];
__device__ float g_score[128 * 128];
__device__ float g_sA[4096];
__device__ float g_sB[8192];

__device__ uint4 g_Aq1[4096 * 512 / 16];
__device__ uint4 g_Aq2[4096 * 512 / 16];
__device__ uint4 g_Bq1[8192 * 512 / 16];
__device__ uint4 g_Bq2[8192 * 512 / 16];

// ---------------- PTX helpers ----------------
__device__ __forceinline__ uint32_t smem_u32(const void* p) {
    uint32_t a;
    asm("{ .reg .u64 t; cvta.to.shared.u64 t, %1; cvt.u32.u64 %0, t; }" : "=r"(a) : "l"(p));
    return a;
}
#define CP_ASYNC16(dst, src) asm volatile("cp.async.cg.shared.global [%0], [%1], 16;" :: "r"(dst), "l"(src))
#define CP_COMMIT()          asm volatile("cp.async.commit_group;" ::: "memory")
#define CP_WAIT1()           asm volatile("cp.async.wait_group 1;" ::: "memory")
#define CP_WAIT0()           asm volatile("cp.async.wait_group 0;" ::: "memory")
#define LDSM_X4(r0, r1, r2, r3, addr) \
    asm volatile("ldmatrix.sync.aligned.m8n8.x4.shared.b16 {%0,%1,%2,%3}, [%4];" \
        : "=r"(r0), "=r"(r1), "=r"(r2), "=r"(r3) : "r"(addr))
#define MMA_S8(d, a, b0, b1) \
    asm volatile("mma.sync.aligned.m16n8k32.row.col.s32.s8.s8.s32 " \
        "{%0,%1,%2,%3}, {%4,%5,%6,%7}, {%8,%9}, {%0,%1,%2,%3};" \
        : "+r"((d)[0]), "+r"((d)[1]), "+r"((d)[2]), "+r"((d)[3]) \
        : "r"((a)[0]), "r"((a)[1]), "r"((a)[2]), "r"((a)[3]), "r"(b0), "r"(b1))

// ---------------- input disambiguation ----------------
__device__ __forceinline__ bool looks_like_int_small(const unsigned* w, unsigned limit) {
    bool ok = true;
    #pragma unroll
    for (int i = 0; i < 8; i++) ok = ok && (w[i] <= limit);
    return ok;
}
__device__ __forceinline__ bool int_width64(const unsigned* w) {
    return (w[1] == 0u) && (w[3] == 0u) && (w[5] == 0u) && (w[7] == 0u);
}
__device__ __forceinline__ bool int_elem_nonzero(const unsigned* w, int i, bool w64) {
    return w64 ? ((w[2 * i] | w[2 * i + 1]) != 0u) : (w[i] != 0u);
}

// ---------------------------------------------------------------------------
// quant + prep.
// ---------------------------------------------------------------------------
__global__ void __launch_bounds__(256)
quant_prep_kernel(const float* __restrict__ A, const float* __restrict__ B,
                  const void* q0, const void* q1p, const void* r0, const void* r1) {
    bool q0_tok = looks_like_int_small((const unsigned*)q0, 99999u);
    const unsigned* tokw = (const unsigned*)(q0_tok ? q0 : q1p);
    const float*    wtA  = (const float*)(q0_tok ? q1p : q0);
    bool tok64 = int_width64(tokw);
    bool r0_msk = looks_like_int_small((const unsigned*)r0, 1u);
    const unsigned* mskw = (const unsigned*)(r0_msk ? r0 : r1);
    const float*    wtB  = (const float*)(r0_msk ? r1 : r0);
    bool msk64 = int_width64(mskw);

    if (blockIdx.x >= 1536) {
        int row = blockIdx.x - 1536;
        int w = threadIdx.x >> 5, lane = threadIdx.x & 31;
        if (w == 0) {
            float m = int_elem_nonzero(tokw, row * 32 + lane, tok64) ? 1.f : 0.f;
            float x = (m > 0.f) ? wtA[row * 32 + lane] : NEG_BIG;
            float mx = x;
            #pragma unroll
            for (int o = 16; o; o >>= 1) mx = fmaxf(mx, __shfl_xor_sync(0xffffffffu, mx, o));
            float e = expf(x - mx), s = e;
            #pragma unroll
            for (int o = 16; o; o >>= 1) s += __shfl_xor_sync(0xffffffffu, s, o);
            g_wA[row * 32 + lane] = e / s;
        } else if (w == 1) {
            float m0 = int_elem_nonzero(mskw, row * 64 + lane, msk64) ? 1.f : 0.f;
            float m1 = int_elem_nonzero(mskw, row * 64 + lane + 32, msk64) ? 1.f : 0.f;
            float x0 = (m0 > 0.f) ? wtB[row * 64 + lane] : NEG_BIG;
            float x1 = (m1 > 0.f) ? wtB[row * 64 + lane + 32] : NEG_BIG;
            float mx = fmaxf(x0, x1);
            #pragma unroll
            for (int o = 16; o; o >>= 1) mx = fmaxf(mx, __shfl_xor_sync(0xffffffffu, mx, o));
            float e0 = expf(x0 - mx), e1 = expf(x1 - mx);
            float s = e0 + e1;
            #pragma unroll
            for (int o = 16; o; o >>= 1) s += __shfl_xor_sync(0xffffffffu, s, o);
            g_wB[row * 64 + lane] = e0 / s;
            g_wB[row * 64 + lane + 32] = e1 / s;
        }
        return;
    }

    int w = threadIdx.x >> 5, lane = threadIdx.x & 31;
    int row = blockIdx.x * 8 + w;
    bool isA = row < 4096;
    int rloc = isA ? row : row - 4096;
    const float* src = isA ? (A + (size_t)rloc * 512) : (B + (size_t)rloc * 512);
    float m = isA ? (int_elem_nonzero(tokw, rloc, tok64) ? 1.f : 0.f)
                  : (int_elem_nonzero(mskw, rloc, msk64) ? 1.f : 0.f);

    float v[16];
    #pragma unroll
    for (int i = 0; i < 4; i++) {
        float4 x = ((const float4*)src)[lane * 4 + i];
        v[i * 4 + 0] = x.x * m;
        v[i * 4 + 1] = x.y * m;
        v[i * 4 + 2] = x.z * m;
        v[i * 4 + 3] = x.w * m;
    }
    float amax = 0.f;
    #pragma unroll
    for (int i = 0; i < 16; i++) amax = fmaxf(amax, fabsf(v[i]));
    #pragma unroll
    for (int o = 16; o; o >>= 1) amax = fmaxf(amax, __shfl_xor_sync(0xffffffffu, amax, o));

    float sInv = (amax > 0.f) ? (127.f / amax) : 0.f;
    float s = amax * (1.f / 127.f);

    uint32_t p1[4], p2[4];
    #pragma unroll
    for (int g = 0; g < 4; g++) {
        uint32_t u1 = 0, u2 = 0;
        #pragma unroll
        for (int k = 0; k < 4; k++) {
            float x = v[g * 4 + k];
            float f1 = rintf(x * sInv);
            f1 = fminf(fmaxf(f1, -127.f), 127.f);
            int i1 = (int)f1;
            float r = fmaf(-f1, s, x);
            float f2 = rintf(r * 254.f * sInv);
            f2 = fminf(fmaxf(f2, -127.f), 127.f);
            int i2 = (int)f2;
            u1 |= ((uint32_t)(uint8_t)i1) << (k * 8);
            u2 |= ((uint32_t)(uint8_t)i2) << (k * 8);
        }
        p1[g] = u1; p2[g] = u2;
    }
    uint4 pk1 = make_uint4(p1[0], p1[1], p1[2], p1[3]);
    uint4 pk2 = make_uint4(p2[0], p2[1], p2[2], p2[3]);
    size_t idx = (size_t)rloc * 32 + lane;
    if (isA) { g_Aq1[idx] = pk1; g_Aq2[idx] = pk2; }
    else     { g_Bq1[idx] = pk1; g_Bq2[idx] = pk2; }
    if (lane == 0) { if (isA) g_sA[rloc] = s; else g_sB[rloc] = s; }
}

// ---------------------------------------------------------------------------
// Persistent GEMM.  296 CTAs, 2/SM.  Tiles 128x64 (4096 total), ~14 per CTA.
// K=512 in 4 chunks of 128 int8.  2-stage cp.async indexed by a GLOBAL chunk
// counter that runs continuously across tiles.  Epilogue scratch lives past
// the stages so it overlaps in-flight copies for the next tile.
// ---------------------------------------------------------------------------
#define AQ1_OFF 0
#define AQ2_OFF 16384
#define BQ1_OFF 32768
#define BQ2_OFF 40960
#define STAGE_BYTES 49152
#define SCRATCH_OFF (2 * STAGE_BYTES)
#define GEMM_SMEM (2 * STAGE_BYTES + 2048)
#define NSLOT 296
#define NTILES 4096

__device__ __forceinline__ void issue_copies(uint32_t sb, int m0, int n0, int ck, int tid) {
    const char* sA1 = (const char*)g_Aq1;
    const char* sA2 = (const char*)g_Aq2;
    const char* sB1 = (const char*)g_Bq1;
    const char* sB2 = (const char*)g_Bq2;
    #pragma unroll
    for (int i = 0; i < 4; i++) {
        int u = tid + 256 * i, r = u >> 3, c = u & 7;
        uint32_t d = sb + AQ1_OFF + (uint32_t)(r * 128 + ((c ^ (r & 7)) * 16));
        CP_ASYNC16(d, sA1 + (size_t)(m0 + r) * 512 + ck * 128 + c * 16);
    }
    #pragma unroll
    for (int i = 0; i < 4; i++) {
        int u = tid + 256 * i, r = u >> 3, c = u & 7;
        uint32_t d = sb + AQ2_OFF + (uint32_t)(r * 128 + ((c ^ (r & 7)) * 16));
        CP_ASYNC16(d, sA2 + (size_t)(m0 + r) * 512 + ck * 128 + c * 16);
    }
    #pragma unroll
    for (int i = 0; i < 2; i++) {
        int u = tid + 256 * i, r = u >> 3, c = u & 7;
        uint32_t d = sb + BQ1_OFF + (uint32_t)(r * 128 + ((c ^ (r & 7)) * 16));
        CP_ASYNC16(d, sB1 + (size_t)(n0 + r) * 512 + ck * 128 + c * 16);
    }
    #pragma unroll
    for (int i = 0; i < 2; i++) {
        int u = tid + 256 * i, r = u >> 3, c = u & 7;
        uint32_t d = sb + BQ2_OFF + (uint32_t)(r * 128 + ((c ^ (r & 7)) * 16));
        CP_ASYNC16(d, sB2 + (size_t)(n0 + r) * 512 + ck * 128 + c * 16);
    }
}

// global chunk g -> (m0, n0, ck) for this CTA
__device__ __forceinline__ void chunk_coords(int bid, int g, int& m0, int& n0, int& ck) {
    int t = bid + (g >> 2) * NSLOT;       // tile id
    m0 = (t >> 7) * 128;
    n0 = (t & 127) * 64;
    ck = g & 3;
}

__global__ void __launch_bounds__(256, 2)
gemm_kernel() {
    extern __shared__ __align__(1024) char dyn[];
    uint32_t base = smem_u32(dyn);

    int tid = threadIdx.x;
    int w = tid >> 5, lane = tid & 31;
    int wm = w >> 1, wn = w & 1;
    int q = lane >> 2, t4 = lane & 3;
    int bid = blockIdx.x;

    int my_n = (NTILES - bid + NSLOT - 1) / NSLOT;
    int total_chunks = my_n * 4;

    int acc1[2][4][4], acc2[2][4][4];
    #pragma unroll
    for (int i = 0; i < 2; i++)
        #pragma unroll
        for (int j = 0; j < 4; j++)
            #pragma unroll
            for (int e = 0; e < 4; e++) { acc1[i][j][e] = 0; acc2[i][j][e] = 0; }

    // prologue: global chunks 0, 1
    {
        int m0, n0, ck;
        chunk_coords(bid, 0, m0, n0, ck);
        issue_copies(base + 0 * STAGE_BYTES, m0, n0, ck, tid);
        CP_COMMIT();
        chunk_coords(bid, 1, m0, n0, ck);
        issue_copies(base + 1 * STAGE_BYTES, m0, n0, ck, tid);
        CP_COMMIT();
    }

    int aRow = wm * 32 + ((lane >> 3) & 1) * 8 + (lane & 7);
    int aUsel = lane >> 4;
    int bRow = wn * 32 + lane;

    float* rowred = (float*)(dyn + SCRATCH_OFF);          // [128][2]
    float* colred = (float*)(dyn + SCRATCH_OFF) + 256;    // [64][4]

    for (int g = 0; g < total_chunks; g++) {
        uint32_t sb = base + (uint32_t)(g & 1) * STAGE_BYTES;
        if (g < total_chunks - 1) { CP_WAIT1(); } else { CP_WAIT0(); }
        __syncthreads();

        #pragma unroll
        for (int ks = 0; ks < 4; ks++) {
            int ub = ks * 2;
            uint32_t a1f[2][4], a2f[2][4];
            #pragma unroll
            for (int mi = 0; mi < 2; mi++) {
                int row = aRow + mi * 16;
                uint32_t su = (uint32_t)((ub + aUsel) ^ (row & 7)) * 16;
                uint32_t ad = sb + (uint32_t)(row * 128) + su;
                LDSM_X4(a1f[mi][0], a1f[mi][1], a1f[mi][2], a1f[mi][3], ad + AQ1_OFF);
                LDSM_X4(a2f[mi][0], a2f[mi][1], a2f[mi][2], a2f[mi][3], ad + AQ2_OFF);
            }
            uint32_t b1u0[4], b1u1[4], b2u0[4], b2u1[4];
            {
                uint32_t su0 = (uint32_t)(ub ^ (lane & 7)) * 16;
                uint32_t su1 = (uint32_t)((ub + 1) ^ (lane & 7)) * 16;
                uint32_t bd = sb + (uint32_t)(bRow * 128);
                LDSM_X4(b1u0[0], b1u0[1], b1u0[2], b1u0[3], bd + BQ1_OFF + su0);
                LDSM_X4(b1u1[0], b1u1[1], b1u1[2], b1u1[3], bd + BQ1_OFF + su1);
                LDSM_X4(b2u0[0], b2u0[1], b2u0[2], b2u0[3], bd + BQ2_OFF + su0);
                LDSM_X4(b2u1[0], b2u1[1], b2u1[2], b2u1[3], bd + BQ2_OFF + su1);
            }
            #pragma unroll
            for (int mi = 0; mi < 2; mi++)
                #pragma unroll
                for (int j = 0; j < 4; j++) {
                    MMA_S8(acc1[mi][j], a1f[mi], b1u0[j], b1u1[j]);
                    MMA_S8(acc2[mi][j], a1f[mi], b2u0[j], b2u1[j]);
                    MMA_S8(acc2[mi][j], a2f[mi], b1u0[j], b1u1[j]);
                }
        }
        __syncthreads();
        if (g + 2 < total_chunks) {
            int m0, n0, ck;
            chunk_coords(bid, g + 2, m0, n0, ck);
            issue_copies(base + (uint32_t)((g + 2) & 1) * STAGE_BYTES, m0, n0, ck, tid);
            CP_COMMIT();
        }

        if ((g & 3) == 3) {
            // -------- epilogue for the tile just finished (overlaps copies) ----
            int m0, n0, ckd;
            chunk_coords(bid, g, m0, n0, ckd);
            const float inv254 = 1.f / 254.f;
            float sAv[2][2];
            #pragma unroll
            for (int mi = 0; mi < 2; mi++)
                #pragma unroll
                for (int rh = 0; rh < 2; rh++)
                    sAv[mi][rh] = g_sA[m0 + wm * 32 + mi * 16 + q + rh * 8];
            float sBv[4][2];
            #pragma unroll
            for (int j = 0; j < 4; j++)
                #pragma unroll
                for (int cp = 0; cp < 2; cp++)
                    sBv[j][cp] = g_sB[n0 + wn * 32 + j * 8 + t4 * 2 + cp];

            float sc[2][4][4];
            #pragma unroll
            for (int mi = 0; mi < 2; mi++)
                #pragma unroll
                for (int j = 0; j < 4; j++)
                    #pragma unroll
                    for (int e = 0; e < 4; e++) {
                        float v = __int2float_rn(acc1[mi][j][e]) + __int2float_rn(acc2[mi][j][e]) * inv254;
                        sc[mi][j][e] = sAv[mi][e >> 1] * sBv[j][e & 1] * v;
                        acc1[mi][j][e] = 0; acc2[mi][j][e] = 0;   // reset for next tile
                    }

            #pragma unroll
            for (int mi = 0; mi < 2; mi++) {
                #pragma unroll
                for (int rh = 0; rh < 2; rh++) {
                    float m = fmaxf(sc[mi][0][rh * 2], sc[mi][0][rh * 2 + 1]);
                    #pragma unroll
                    for (int j = 1; j < 4; j++)
                        m = fmaxf(m, fmaxf(sc[mi][j][rh * 2], sc[mi][j][rh * 2 + 1]));
                    m = fmaxf(m, __shfl_xor_sync(0xffffffffu, m, 1));
                    m = fmaxf(m, __shfl_xor_sync(0xffffffffu, m, 2));
                    if (t4 == 0) rowred[(wm * 32 + mi * 16 + q + rh * 8) * 2 + wn] = m;
                }
            }
            #pragma unroll
            for (int j = 0; j < 4; j++) {
                #pragma unroll
                for (int cp = 0; cp < 2; cp++) {
                    float m = fmaxf(fmaxf(sc[0][j][cp], sc[0][j][cp + 2]),
                                    fmaxf(sc[1][j][cp], sc[1][j][cp + 2]));
                    m = fmaxf(m, __shfl_xor_sync(0xffffffffu, m, 4));
                    m = fmaxf(m, __shfl_xor_sync(0xffffffffu, m, 8));
                    m = fmaxf(m, __shfl_xor_sync(0xffffffffu, m, 16));
                    if (q == 0) colred[(wn * 32 + j * 8 + t4 * 2 + cp) * 4 + wm] = m;
                }
            }
            __syncthreads();

            if (w < 4) {
                int a = w;
                int aG = (m0 >> 5) + a;          // m0/128*4 + a
                int bG = n0 >> 6;
                float rf = fmaxf(rowred[(a * 32 + lane) * 2 + 0],
                                 rowred[(a * 32 + lane) * 2 + 1]);
                float val = rf * g_wA[aG * 32 + lane];
                val += colred[lane * 4 + a]        * g_wB[bG * 64 + lane];
                val += colred[(lane + 32) * 4 + a] * g_wB[bG * 64 + lane + 32];
                #pragma unroll
                for (int o = 16; o; o >>= 1) val += __shfl_xor_sync(0xffffffffu, val, o);
                if (lane == 0) g_score[aG * 128 + bG] = 0.5f * val;
            }
        }
    }
}

// ---------------------------------------------------------------------------
// loss: smem-staged.
// ---------------------------------------------------------------------------
#define LOSS_SMEM (16384 * 4 + 256 * 4)
__global__ void loss_kernel(const float* __restrict__ temp, float* __restrict__ out) {
    extern __shared__ __align__(16) float ls[];
    float* red = ls + 16384;
    int tid = threadIdx.x;
    float invT = 1.0f / temp[0];

    float4* d4 = (float4*)ls;
    const float4* s4 = (const float4*)g_score;
    for (int i = tid; i < 4096; i += 256) d4[i] = s4[i];
    __syncthreads();

    int i = tid & 127;
    bool isRow = tid < 128;
    float mx = NEG_BIG;
    #pragma unroll 4
    for (int j = 0; j < 128; j++) {
        float x = isRow ? ls[i * 128 + j] : ls[j * 128 + i];
        mx = fmaxf(mx, x);
    }
    float s = 0.f;
    #pragma unroll 4
    for (int j = 0; j < 128; j++) {
        float x = isRow ? ls[i * 128 + j] : ls[j * 128 + i];
        s += expf((x - mx) * invT);
    }
    float lse = mx * invT + logf(s);
    float diag = ls[i * 128 + i] * invT;
    red[tid] = lse - diag;
    __syncthreads();
    for (int o = 128; o; o >>= 1) {
        if (tid < o) red[tid] += red[tid + o];
        __syncthreads();
    }
    if (tid == 0) out[0] = red[0] / 256.f;
}

// ---------------------------------------------------------------------------
extern "C" void kernel_launch(void* const* d_in, const int* in_sizes, int n_in,
                              void* d_out, int out_size) {
    (void)out_size;
    int order[7];
    for (int i = 0; i < 7 && i < n_in; i++) order[i] = i;
    for (int i = 1; i < 7; i++) {
        int o = order[i];
        long long s = in_sizes[o];
        int j = i - 1;
        while (j >= 0 && (long long)in_sizes[order[j]] > s) { order[j + 1] = order[j]; j--; }
        order[j + 1] = o;
    }
    const float* temp  = (const float*)d_in[order[0]];
    const void*  q0    = d_in[order[1]];
    const void*  q1    = d_in[order[2]];
    const void*  r0    = d_in[order[3]];
    const void*  r1    = d_in[order[4]];
    const float* featA = (const float*)d_in[order[5]];
    const float* featB = (const float*)d_in[order[6]];
    float* out = (float*)d_out;

    static bool attrSet = false;
    if (!attrSet) {
        cudaFuncSetAttribute(gemm_kernel, cudaFuncAttributeMaxDynamicSharedMemorySize, GEMM_SMEM);
        cudaFuncSetAttribute(loss_kernel, cudaFuncAttributeMaxDynamicSharedMemorySize, LOSS_SMEM);
        attrSet = true;
    }

    quant_prep_kernel<<<1664, 256>>>(featA, featB, q0, q1, r0, r1);
    gemm_kernel<<<NSLOT, 256, GEMM_SMEM>>>();
    loss_kernel<<<1, 256, LOSS_SMEM>>>(temp, out);
}

// round 11
// speedup vs baseline: 1.0103x; 1.0103x over previous
#include <cuda_runtime.h>
#include <math.h>
#include <stdint.h>

// ---------------------------------------------------------------------------
// B=128, T=32, V=64, D=512.  score[128][128].
// sm_100 BASELINE target: mma.sync s8 (m16n8k32) + cp.async + ldmatrix.
// 2-level int8 row-scaled split:  x = s*(q1 + q2/254) + O(s/508)
//   score = sA[r]*sB[c]*( Σq1a*q1b + (Σq1a*q2b + Σq2a*q1b)/254 )
//   quant_prep:  per-row amax+quantize to q1/q2 int8 + scales; softmax weights
//   gemm_kernel: 128x64 tile/CTA (grid 128x32), 2 CTAs/SM, 2-stage cp.async,
//                fused scale+max epilogue -> score[a][b]; LAST CTA computes
//                the final log-softmax loss in-kernel (counter + fence).
// ---------------------------------------------------------------------------

#define NEG_BIG (-3.0e38f)
#define NTOT 4096           // total GEMM CTAs (128 x 32)

__device__ float g_wA[128 * 32];
__device__ float g_wB[128 * 64];
__device__ float g_score[128 * 128];
__device__ float g_sA[4096];
__device__ float g_sB[8192];
__device__ unsigned g_done = 0;

__device__ uint4 g_Aq1[4096 * 512 / 16];
__device__ uint4 g_Aq2[4096 * 512 / 16];
__device__ uint4 g_Bq1[8192 * 512 / 16];
__device__ uint4 g_Bq2[8192 * 512 / 16];

// ---------------- PTX helpers ----------------
__device__ __forceinline__ uint32_t smem_u32(const void* p) {
    uint32_t a;
    asm("{ .reg .u64 t; cvta.to.shared.u64 t, %1; cvt.u32.u64 %0, t; }" : "=r"(a) : "l"(p));
    return a;
}
__device__ __forceinline__ uint32_t prmt(uint32_t a, uint32_t b, uint32_t s) {
    uint32_t r;
    asm("prmt.b32 %0, %1, %2, %3;" : "=r"(r) : "r"(a), "r"(b), "r"(s));
    return r;
}
#define CP_ASYNC16(dst, src) asm volatile("cp.async.cg.shared.global [%0], [%1], 16;" :: "r"(dst), "l"(src))
#define CP_COMMIT()          asm volatile("cp.async.commit_group;" ::: "memory")
#define CP_WAIT1()           asm volatile("cp.async.wait_group 1;" ::: "memory")
#define CP_WAIT0()           asm volatile("cp.async.wait_group 0;" ::: "memory")
#define LDSM_X4(r0, r1, r2, r3, addr) \
    asm volatile("ldmatrix.sync.aligned.m8n8.x4.shared.b16 {%0,%1,%2,%3}, [%4];" \
        : "=r"(r0), "=r"(r1), "=r"(r2), "=r"(r3) : "r"(addr))
#define MMA_S8(d, a, b0, b1) \
    asm volatile("mma.sync.aligned.m16n8k32.row.col.s32.s8.s8.s32 " \
        "{%0,%1,%2,%3}, {%4,%5,%6,%7}, {%8,%9}, {%0,%1,%2,%3};" \
        : "+r"((d)[0]), "+r"((d)[1]), "+r"((d)[2]), "+r"((d)[3]) \
        : "r"((a)[0]), "r"((a)[1]), "r"((a)[2]), "r"((a)[3]), "r"(b0), "r"(b1))

// ---------------- input disambiguation ----------------
__device__ __forceinline__ bool looks_like_int_small(const unsigned* w, unsigned limit) {
    bool ok = true;
    #pragma unroll
    for (int i = 0; i < 8; i++) ok = ok && (w[i] <= limit);
    return ok;
}
__device__ __forceinline__ bool int_width64(const unsigned* w) {
    return (w[1] == 0u) && (w[3] == 0u) && (w[5] == 0u) && (w[7] == 0u);
}
__device__ __forceinline__ bool int_elem_nonzero(const unsigned* w, int i, bool w64) {
    return w64 ? ((w[2 * i] | w[2 * i + 1]) != 0u) : (w[i] != 0u);
}

// ---------------------------------------------------------------------------
// quant + prep.  Blocks [0,1536): one warp per feature row (12288 rows).
// Blocks [1536,1664): masked-softmax weights.
// ---------------------------------------------------------------------------
__global__ void __launch_bounds__(256)
quant_prep_kernel(const float* __restrict__ A, const float* __restrict__ B,
                  const void* q0, const void* q1p, const void* r0, const void* r1) {
    bool q0_tok = looks_like_int_small((const unsigned*)q0, 99999u);
    const unsigned* tokw = (const unsigned*)(q0_tok ? q0 : q1p);
    const float*    wtA  = (const float*)(q0_tok ? q1p : q0);
    bool tok64 = int_width64(tokw);
    bool r0_msk = looks_like_int_small((const unsigned*)r0, 1u);
    const unsigned* mskw = (const unsigned*)(r0_msk ? r0 : r1);
    const float*    wtB  = (const float*)(r0_msk ? r1 : r0);
    bool msk64 = int_width64(mskw);

    if (blockIdx.x >= 1536) {
        int row = blockIdx.x - 1536;
        int w = threadIdx.x >> 5, lane = threadIdx.x & 31;
        if (w == 0) {
            float m = int_elem_nonzero(tokw, row * 32 + lane, tok64) ? 1.f : 0.f;
            float x = (m > 0.f) ? wtA[row * 32 + lane] : NEG_BIG;
            float mx = x;
            #pragma unroll
            for (int o = 16; o; o >>= 1) mx = fmaxf(mx, __shfl_xor_sync(0xffffffffu, mx, o));
            float e = expf(x - mx), s = e;
            #pragma unroll
            for (int o = 16; o; o >>= 1) s += __shfl_xor_sync(0xffffffffu, s, o);
            g_wA[row * 32 + lane] = e / s;
        } else if (w == 1) {
            float m0 = int_elem_nonzero(mskw, row * 64 + lane, msk64) ? 1.f : 0.f;
            float m1 = int_elem_nonzero(mskw, row * 64 + lane + 32, msk64) ? 1.f : 0.f;
            float x0 = (m0 > 0.f) ? wtB[row * 64 + lane] : NEG_BIG;
            float x1 = (m1 > 0.f) ? wtB[row * 64 + lane + 32] : NEG_BIG;
            float mx = fmaxf(x0, x1);
            #pragma unroll
            for (int o = 16; o; o >>= 1) mx = fmaxf(mx, __shfl_xor_sync(0xffffffffu, mx, o));
            float e0 = expf(x0 - mx), e1 = expf(x1 - mx);
            float s = e0 + e1;
            #pragma unroll
            for (int o = 16; o; o >>= 1) s += __shfl_xor_sync(0xffffffffu, s, o);
            g_wB[row * 64 + lane] = e0 / s;
            g_wB[row * 64 + lane + 32] = e1 / s;
        }
        return;
    }

    int w = threadIdx.x >> 5, lane = threadIdx.x & 31;
    int row = blockIdx.x * 8 + w;
    bool isA = row < 4096;
    int rloc = isA ? row : row - 4096;
    const float* src = isA ? (A + (size_t)rloc * 512) : (B + (size_t)rloc * 512);
    float m = isA ? (int_elem_nonzero(tokw, rloc, tok64) ? 1.f : 0.f)
                  : (int_elem_nonzero(mskw, rloc, msk64) ? 1.f : 0.f);

    float v[16];
    #pragma unroll
    for (int i = 0; i < 4; i++) {
        float4 x = ((const float4*)src)[lane * 4 + i];
        v[i * 4 + 0] = x.x * m;
        v[i * 4 + 1] = x.y * m;
        v[i * 4 + 2] = x.z * m;
        v[i * 4 + 3] = x.w * m;
    }
    float amax = 0.f;
    #pragma unroll
    for (int i = 0; i < 16; i++) amax = fmaxf(amax, fabsf(v[i]));
    #pragma unroll
    for (int o = 16; o; o >>= 1) amax = fmaxf(amax, __shfl_xor_sync(0xffffffffu, amax, o));

    float sInv = (amax > 0.f) ? (127.f / amax) : 0.f;
    float s = amax * (1.f / 127.f);

    uint32_t p1[4], p2[4];
    #pragma unroll
    for (int g = 0; g < 4; g++) {
        uint32_t i1v[4], i2v[4];
        #pragma unroll
        for (int k = 0; k < 4; k++) {
            float x = v[g * 4 + k];
            float f1 = rintf(x * sInv);
            f1 = fminf(fmaxf(f1, -127.f), 127.f);
            int i1 = (int)f1;
            float r = fmaf(-f1, s, x);
            float f2 = rintf(r * 254.f * sInv);
            f2 = fminf(fmaxf(f2, -127.f), 127.f);
            int i2 = (int)f2;
            i1v[k] = (uint32_t)i1;
            i2v[k] = (uint32_t)i2;
        }
        p1[g] = prmt(prmt(i1v[0], i1v[1], 0x0040u), prmt(i1v[2], i1v[3], 0x0040u), 0x5410u);
        p2[g] = prmt(prmt(i2v[0], i2v[1], 0x0040u), prmt(i2v[2], i2v[3], 0x0040u), 0x5410u);
    }
    uint4 pk1 = make_uint4(p1[0], p1[1], p1[2], p1[3]);
    uint4 pk2 = make_uint4(p2[0], p2[1], p2[2], p2[3]);
    size_t idx = (size_t)rloc * 32 + lane;
    if (isA) { g_Aq1[idx] = pk1; g_Aq2[idx] = pk2; }
    else     { g_Bq1[idx] = pk1; g_Bq2[idx] = pk2; }
    if (lane == 0) { if (isA) g_sA[rloc] = s; else g_sB[rloc] = s; }
}

// ---------------------------------------------------------------------------
// GEMM: 128x64 tile/CTA, 2 CTAs/SM, grid (128 n, 32 m).  256 threads,
// 8 warps = 4 row-bands x 2 col-bands (warp tile 32x32).  K=512 in 4 chunks
// of 128 int8 (SW128).  2-stage cp.async.  Fused epilogue -> g_score.
// LAST finishing CTA computes the loss (counter + fences) and resets counter.
// ---------------------------------------------------------------------------
#define AQ1_OFF 0
#define AQ2_OFF 16384
#define BQ1_OFF 32768
#define BLQ2_OFF 40960
#define STAGE_BYTES 49152
#define GEMM_SMEM (2 * STAGE_BYTES)

__device__ __forceinline__ void issue_copies(uint32_t sb, int m0, int n0, int ck, int tid) {
    const char* sA1 = (const char*)g_Aq1;
    const char* sA2 = (const char*)g_Aq2;
    const char* sB1 = (const char*)g_Bq1;
    const char* sB2 = (const char*)g_Bq2;
    #pragma unroll
    for (int i = 0; i < 4; i++) {
        int u = tid + 256 * i, r = u >> 3, c = u & 7;
        uint32_t d = sb + AQ1_OFF + (uint32_t)(r * 128 + ((c ^ (r & 7)) * 16));
        CP_ASYNC16(d, sA1 + (size_t)(m0 + r) * 512 + ck * 128 + c * 16);
    }
    #pragma unroll
    for (int i = 0; i < 4; i++) {
        int u = tid + 256 * i, r = u >> 3, c = u & 7;
        uint32_t d = sb + AQ2_OFF + (uint32_t)(r * 128 + ((c ^ (r & 7)) * 16));
        CP_ASYNC16(d, sA2 + (size_t)(m0 + r) * 512 + ck * 128 + c * 16);
    }
    #pragma unroll
    for (int i = 0; i < 2; i++) {
        int u = tid + 256 * i, r = u >> 3, c = u & 7;
        uint32_t d = sb + BQ1_OFF + (uint32_t)(r * 128 + ((c ^ (r & 7)) * 16));
        CP_ASYNC16(d, sB1 + (size_t)(n0 + r) * 512 + ck * 128 + c * 16);
    }
    #pragma unroll
    for (int i = 0; i < 2; i++) {
        int u = tid + 256 * i, r = u >> 3, c = u & 7;
        uint32_t d = sb + BLQ2_OFF + (uint32_t)(r * 128 + ((c ^ (r & 7)) * 16));
        CP_ASYNC16(d, sB2 + (size_t)(n0 + r) * 512 + ck * 128 + c * 16);
    }
}

__global__ void __launch_bounds__(256, 2)
gemm_kernel(const float* __restrict__ temp, float* __restrict__ out) {
    extern __shared__ __align__(1024) char dyn[];
    uint32_t base = smem_u32(dyn);

    int tid = threadIdx.x;
    int w = tid >> 5, lane = tid & 31;
    int wm = w >> 1, wn = w & 1;
    int q = lane >> 2, t4 = lane & 3;
    int m0 = blockIdx.y * 128, n0 = blockIdx.x * 64;

    int acc1[2][4][4], acc2[2][4][4];
    #pragma unroll
    for (int i = 0; i < 2; i++)
        #pragma unroll
        for (int j = 0; j < 4; j++)
            #pragma unroll
            for (int e = 0; e < 4; e++) { acc1[i][j][e] = 0; acc2[i][j][e] = 0; }

    issue_copies(base + 0 * STAGE_BYTES, m0, n0, 0, tid);
    CP_COMMIT();
    issue_copies(base + 1 * STAGE_BYTES, m0, n0, 1, tid);
    CP_COMMIT();

    int aRow = wm * 32 + ((lane >> 3) & 1) * 8 + (lane & 7);
    int aUsel = lane >> 4;
    int bRow = wn * 32 + lane;

    for (int ck = 0; ck < 4; ck++) {
        uint32_t sb = base + (uint32_t)(ck & 1) * STAGE_BYTES;
        if (ck < 3) { CP_WAIT1(); } else { CP_WAIT0(); }
        __syncthreads();

        #pragma unroll
        for (int ks = 0; ks < 4; ks++) {
            int ub = ks * 2;
            uint32_t a1f[2][4], a2f[2][4];
            #pragma unroll
            for (int mi = 0; mi < 2; mi++) {
                int row = aRow + mi * 16;
                uint32_t su = (uint32_t)((ub + aUsel) ^ (row & 7)) * 16;
                uint32_t ad = sb + (uint32_t)(row * 128) + su;
                LDSM_X4(a1f[mi][0], a1f[mi][1], a1f[mi][2], a1f[mi][3], ad + AQ1_OFF);
                LDSM_X4(a2f[mi][0], a2f[mi][1], a2f[mi][2], a2f[mi][3], ad + AQ2_OFF);
            }
            uint32_t b1u0[4], b1u1[4], b2u0[4], b2u1[4];
            {
                uint32_t su0 = (uint32_t)(ub ^ (lane & 7)) * 16;
                uint32_t su1 = (uint32_t)((ub + 1) ^ (lane & 7)) * 16;
                uint32_t bd = sb + (uint32_t)(bRow * 128);
                LDSM_X4(b1u0[0], b1u0[1], b1u0[2], b1u0[3], bd + BQ1_OFF + su0);
                LDSM_X4(b1u1[0], b1u1[1], b1u1[2], b1u1[3], bd + BQ1_OFF + su1);
                LDSM_X4(b2u0[0], b2u0[1], b2u0[2], b2u0[3], bd + BLQ2_OFF + su0);
                LDSM_X4(b2u1[0], b2u1[1], b2u1[2], b2u1[3], bd + BLQ2_OFF + su1);
            }
            #pragma unroll
            for (int mi = 0; mi < 2; mi++)
                #pragma unroll
                for (int j = 0; j < 4; j++) {
                    MMA_S8(acc1[mi][j], a1f[mi], b1u0[j], b1u1[j]);
                    MMA_S8(acc2[mi][j], a1f[mi], b2u0[j], b2u1[j]);
                    MMA_S8(acc2[mi][j], a2f[mi], b1u0[j], b1u1[j]);
                }
        }
        __syncthreads();
        if (ck + 2 < 4) {
            issue_copies(sb, m0, n0, ck + 2, tid);
            CP_COMMIT();
        }
    }

    // ---------------- fused epilogue (scales + max reductions) ----------------
    const float inv254 = 1.f / 254.f;
    float sAv[2][2];
    #pragma unroll
    for (int mi = 0; mi < 2; mi++)
        #pragma unroll
        for (int rh = 0; rh < 2; rh++)
            sAv[mi][rh] = g_sA[m0 + wm * 32 + mi * 16 + q + rh * 8];
    float sBv[4][2];
    #pragma unroll
    for (int j = 0; j < 4; j++)
        #pragma unroll
        for (int cp = 0; cp < 2; cp++)
            sBv[j][cp] = g_sB[n0 + wn * 32 + j * 8 + t4 * 2 + cp];

    float sc[2][4][4];
    #pragma unroll
    for (int mi = 0; mi < 2; mi++)
        #pragma unroll
        for (int j = 0; j < 4; j++)
            #pragma unroll
            for (int e = 0; e < 4; e++) {
                float v = __int2float_rn(acc1[mi][j][e]) + __int2float_rn(acc2[mi][j][e]) * inv254;
                sc[mi][j][e] = sAv[mi][e >> 1] * sBv[j][e & 1] * v;
            }

    float* rowred = (float*)dyn;          // [128 rows][2 wn]
    float* colred = (float*)dyn + 256;    // [64 cols][4 a]

    #pragma unroll
    for (int mi = 0; mi < 2; mi++) {
        #pragma unroll
        for (int rh = 0; rh < 2; rh++) {
            float m = fmaxf(sc[mi][0][rh * 2], sc[mi][0][rh * 2 + 1]);
            #pragma unroll
            for (int j = 1; j < 4; j++)
                m = fmaxf(m, fmaxf(sc[mi][j][rh * 2], sc[mi][j][rh * 2 + 1]));
            m = fmaxf(m, __shfl_xor_sync(0xffffffffu, m, 1));
            m = fmaxf(m, __shfl_xor_sync(0xffffffffu, m, 2));
            if (t4 == 0) rowred[(wm * 32 + mi * 16 + q + rh * 8) * 2 + wn] = m;
        }
    }
    #pragma unroll
    for (int j = 0; j < 4; j++) {
        #pragma unroll
        for (int cp = 0; cp < 2; cp++) {
            float m = fmaxf(fmaxf(sc[0][j][cp], sc[0][j][cp + 2]),
                            fmaxf(sc[1][j][cp], sc[1][j][cp + 2]));
            m = fmaxf(m, __shfl_xor_sync(0xffffffffu, m, 4));
            m = fmaxf(m, __shfl_xor_sync(0xffffffffu, m, 8));
            m = fmaxf(m, __shfl_xor_sync(0xffffffffu, m, 16));
            if (q == 0) colred[(wn * 32 + j * 8 + t4 * 2 + cp) * 4 + wm] = m;
        }
    }
    __syncthreads();

    if (w < 4) {
        int a = w;
        int aG = blockIdx.y * 4 + a;
        int bG = blockIdx.x;
        float rf = fmaxf(rowred[(a * 32 + lane) * 2 + 0],
                         rowred[(a * 32 + lane) * 2 + 1]);
        float val = rf * g_wA[aG * 32 + lane];
        val += colred[lane * 4 + a]        * g_wB[bG * 64 + lane];
        val += colred[(lane + 32) * 4 + a] * g_wB[bG * 64 + lane + 32];
        #pragma unroll
        for (int o = 16; o; o >>= 1) val += __shfl_xor_sync(0xffffffffu, val, o);
        if (lane == 0) g_score[aG * 128 + bG] = 0.5f * val;
    }

    // ---------------- last-CTA fused loss ----------------
    __syncthreads();
    __threadfence();
    __shared__ unsigned lastFlag;
    if (tid == 0) {
        unsigned old = atomicAdd(&g_done, 1u);
        lastFlag = (old == NTOT - 1) ? 1u : 0u;
    }
    __syncthreads();
    if (lastFlag) {
        __threadfence();                       // acquire: see all g_score stores
        float* ls = (float*)dyn;               // 64KB stage smem is dead now
        float* red = ls + 16384;
        float invT = 1.0f / temp[0];

        float4* d4 = (float4*)ls;
        const float4* s4 = (const float4*)g_score;
        for (int i = tid; i < 4096; i += 256) d4[i] = s4[i];
        __syncthreads();

        int i = tid & 127;
        bool isRow = tid < 128;
        float mx = NEG_BIG;
        #pragma unroll 4
        for (int j = 0; j < 128; j++) {
            float x = isRow ? ls[i * 128 + j] : ls[j * 128 + i];
            mx = fmaxf(mx, x);
        }
        float s = 0.f;
        #pragma unroll 4
        for (int j = 0; j < 128; j++) {
            float x = isRow ? ls[i * 128 + j] : ls[j * 128 + i];
            s += expf((x - mx) * invT);
        }
        float lse = mx * invT + logf(s);
        float diag = ls[i * 128 + i] * invT;
        red[tid] = lse - diag;
        __syncthreads();
        for (int o = 128; o; o >>= 1) {
            if (tid < o) red[tid] += red[tid + o];
            __syncthreads();
        }
        if (tid == 0) {
            out[0] = red[0] / 256.f;
            g_done = 0;                        // reset for next graph replay
        }
    }
}

// ---------------------------------------------------------------------------
extern "C" void kernel_launch(void* const* d_in, const int* in_sizes, int n_in,
                              void* d_out, int out_size) {
    (void)out_size;
    int order[7];
    for (int i = 0; i < 7 && i < n_in; i++) order[i] = i;
    for (int i = 1; i < 7; i++) {
        int o = order[i];
        long long s = in_sizes[o];
        int j = i - 1;
        while (j >= 0 && (long long)in_sizes[order[j]] > s) { order[j + 1] = order[j]; j--; }
        order[j + 1] = o;
    }
    const float* temp  = (const float*)d_in[order[0]];
    const void*  q0    = d_in[order[1]];
    const void*  q1    = d_in[order[2]];
    const void*  r0    = d_in[order[3]];
    const void*  r1    = d_in[order[4]];
    const float* featA = (const float*)d_in[order[5]];
    const float* featB = (const float*)d_in[order[6]];
    float* out = (float*)d_out;

    static bool attrSet = false;
    if (!attrSet) {
        cudaFuncSetAttribute(gemm_kernel, cudaFuncAttributeMaxDynamicSharedMemorySize, GEMM_SMEM);
        attrSet = true;
    }

    quant_prep_kernel<<<1664, 256>>>(featA, featB, q0, q1, r0, r1);
    gemm_kernel<<<dim3(128, 32), 256, GEMM_SMEM>>>(temp, out);
}

// round 12
// speedup vs baseline: 1.0667x; 1.0558x over previous
#include <cuda_runtime.h>
#include <math.h>
#include <stdint.h>

// ---------------------------------------------------------------------------
// B=128, T=32, V=64, D=512.  score[128][128].
// sm_100 BASELINE target: mma.sync s8 (m16n8k32) + cp.async + ldmatrix.
// 2-level int8 row-scaled split:  x = s*(q1 + q2/254) + O(s/508)
//   score = sA[r]*sB[c]*( Σq1a*q1b + (Σq1a*q2b + Σq2a*q1b)/254 )
//   quant_prep:  per-row amax+quantize (prmt-packed) + scales; softmax weights
//   gemm_kernel: 128x64 tile/CTA (grid 128x32), 2 CTAs/SM, 2-stage cp.async,
//                fused scale+max epilogue -> score[a][b]   [Round-9 verbatim]
//   loss_kernel: 1024-thread smem-staged log-softmax -> scalar
// ---------------------------------------------------------------------------

#define NEG_BIG (-3.0e38f)

__device__ float g_wA[128 * 32];
__device__ float g_wB[128 * 64];
__device__ float g_score[128 * 128];
__device__ float g_sA[4096];
__device__ float g_sB[8192];

__device__ uint4 g_Aq1[4096 * 512 / 16];
__device__ uint4 g_Aq2[4096 * 512 / 16];
__device__ uint4 g_Bq1[8192 * 512 / 16];
__device__ uint4 g_Bq2[8192 * 512 / 16];

// ---------------- PTX helpers ----------------
__device__ __forceinline__ uint32_t smem_u32(const void* p) {
    uint32_t a;
    asm("{ .reg .u64 t; cvta.to.shared.u64 t, %1; cvt.u32.u64 %0, t; }" : "=r"(a) : "l"(p));
    return a;
}
__device__ __forceinline__ uint32_t prmt(uint32_t a, uint32_t b, uint32_t s) {
    uint32_t r;
    asm("prmt.b32 %0, %1, %2, %3;" : "=r"(r) : "r"(a), "r"(b), "r"(s));
    return r;
}
#define CP_ASYNC16(dst, src) asm volatile("cp.async.cg.shared.global [%0], [%1], 16;" :: "r"(dst), "l"(src))
#define CP_COMMIT()          asm volatile("cp.async.commit_group;" ::: "memory")
#define CP_WAIT1()           asm volatile("cp.async.wait_group 1;" ::: "memory")
#define CP_WAIT0()           asm volatile("cp.async.wait_group 0;" ::: "memory")
#define LDSM_X4(r0, r1, r2, r3, addr) \
    asm volatile("ldmatrix.sync.aligned.m8n8.x4.shared.b16 {%0,%1,%2,%3}, [%4];" \
        : "=r"(r0), "=r"(r1), "=r"(r2), "=r"(r3) : "r"(addr))
#define MMA_S8(d, a, b0, b1) \
    asm volatile("mma.sync.aligned.m16n8k32.row.col.s32.s8.s8.s32 " \
        "{%0,%1,%2,%3}, {%4,%5,%6,%7}, {%8,%9}, {%0,%1,%2,%3};" \
        : "+r"((d)[0]), "+r"((d)[1]), "+r"((d)[2]), "+r"((d)[3]) \
        : "r"((a)[0]), "r"((a)[1]), "r"((a)[2]), "r"((a)[3]), "r"(b0), "r"(b1))

// ---------------- input disambiguation ----------------
__device__ __forceinline__ bool looks_like_int_small(const unsigned* w, unsigned limit) {
    bool ok = true;
    #pragma unroll
    for (int i = 0; i < 8; i++) ok = ok && (w[i] <= limit);
    return ok;
}
__device__ __forceinline__ bool int_width64(const unsigned* w) {
    return (w[1] == 0u) && (w[3] == 0u) && (w[5] == 0u) && (w[7] == 0u);
}
__device__ __forceinline__ bool int_elem_nonzero(const unsigned* w, int i, bool w64) {
    return w64 ? ((w[2 * i] | w[2 * i + 1]) != 0u) : (w[i] != 0u);
}

// ---------------------------------------------------------------------------
// quant + prep.  Blocks [0,1536): one warp per feature row (12288 rows).
// Blocks [1536,1664): masked-softmax weights.
// ---------------------------------------------------------------------------
__global__ void __launch_bounds__(256)
quant_prep_kernel(const float* __restrict__ A, const float* __restrict__ B,
                  const void* q0, const void* q1p, const void* r0, const void* r1) {
    bool q0_tok = looks_like_int_small((const unsigned*)q0, 99999u);
    const unsigned* tokw = (const unsigned*)(q0_tok ? q0 : q1p);
    const float*    wtA  = (const float*)(q0_tok ? q1p : q0);
    bool tok64 = int_width64(tokw);
    bool r0_msk = looks_like_int_small((const unsigned*)r0, 1u);
    const unsigned* mskw = (const unsigned*)(r0_msk ? r0 : r1);
    const float*    wtB  = (const float*)(r0_msk ? r1 : r0);
    bool msk64 = int_width64(mskw);

    if (blockIdx.x >= 1536) {
        int row = blockIdx.x - 1536;
        int w = threadIdx.x >> 5, lane = threadIdx.x & 31;
        if (w == 0) {
            float m = int_elem_nonzero(tokw, row * 32 + lane, tok64) ? 1.f : 0.f;
            float x = (m > 0.f) ? wtA[row * 32 + lane] : NEG_BIG;
            float mx = x;
            #pragma unroll
            for (int o = 16; o; o >>= 1) mx = fmaxf(mx, __shfl_xor_sync(0xffffffffu, mx, o));
            float e = expf(x - mx), s = e;
            #pragma unroll
            for (int o = 16; o; o >>= 1) s += __shfl_xor_sync(0xffffffffu, s, o);
            g_wA[row * 32 + lane] = e / s;
        } else if (w == 1) {
            float m0 = int_elem_nonzero(mskw, row * 64 + lane, msk64) ? 1.f : 0.f;
            float m1 = int_elem_nonzero(mskw, row * 64 + lane + 32, msk64) ? 1.f : 0.f;
            float x0 = (m0 > 0.f) ? wtB[row * 64 + lane] : NEG_BIG;
            float x1 = (m1 > 0.f) ? wtB[row * 64 + lane + 32] : NEG_BIG;
            float mx = fmaxf(x0, x1);
            #pragma unroll
            for (int o = 16; o; o >>= 1) mx = fmaxf(mx, __shfl_xor_sync(0xffffffffu, mx, o));
            float e0 = expf(x0 - mx), e1 = expf(x1 - mx);
            float s = e0 + e1;
            #pragma unroll
            for (int o = 16; o; o >>= 1) s += __shfl_xor_sync(0xffffffffu, s, o);
            g_wB[row * 64 + lane] = e0 / s;
            g_wB[row * 64 + lane + 32] = e1 / s;
        }
        return;
    }

    int w = threadIdx.x >> 5, lane = threadIdx.x & 31;
    int row = blockIdx.x * 8 + w;
    bool isA = row < 4096;
    int rloc = isA ? row : row - 4096;
    const float* src = isA ? (A + (size_t)rloc * 512) : (B + (size_t)rloc * 512);
    float m = isA ? (int_elem_nonzero(tokw, rloc, tok64) ? 1.f : 0.f)
                  : (int_elem_nonzero(mskw, rloc, msk64) ? 1.f : 0.f);

    float v[16];
    #pragma unroll
    for (int i = 0; i < 4; i++) {
        float4 x = ((const float4*)src)[lane * 4 + i];
        v[i * 4 + 0] = x.x * m;
        v[i * 4 + 1] = x.y * m;
        v[i * 4 + 2] = x.z * m;
        v[i * 4 + 3] = x.w * m;
    }
    float amax = 0.f;
    #pragma unroll
    for (int i = 0; i < 16; i++) amax = fmaxf(amax, fabsf(v[i]));
    #pragma unroll
    for (int o = 16; o; o >>= 1) amax = fmaxf(amax, __shfl_xor_sync(0xffffffffu, amax, o));

    float sInv = (amax > 0.f) ? (127.f / amax) : 0.f;
    float s = amax * (1.f / 127.f);

    uint32_t p1[4], p2[4];
    #pragma unroll
    for (int g = 0; g < 4; g++) {
        uint32_t i1v[4], i2v[4];
        #pragma unroll
        for (int k = 0; k < 4; k++) {
            float x = v[g * 4 + k];
            float f1 = rintf(x * sInv);
            f1 = fminf(fmaxf(f1, -127.f), 127.f);
            int i1 = (int)f1;
            float r = fmaf(-f1, s, x);
            float f2 = rintf(r * 254.f * sInv);
            f2 = fminf(fmaxf(f2, -127.f), 127.f);
            int i2 = (int)f2;
            i1v[k] = (uint32_t)i1;
            i2v[k] = (uint32_t)i2;
        }
        p1[g] = prmt(prmt(i1v[0], i1v[1], 0x0040u), prmt(i1v[2], i1v[3], 0x0040u), 0x5410u);
        p2[g] = prmt(prmt(i2v[0], i2v[1], 0x0040u), prmt(i2v[2], i2v[3], 0x0040u), 0x5410u);
    }
    uint4 pk1 = make_uint4(p1[0], p1[1], p1[2], p1[3]);
    uint4 pk2 = make_uint4(p2[0], p2[1], p2[2], p2[3]);
    size_t idx = (size_t)rloc * 32 + lane;
    if (isA) { g_Aq1[idx] = pk1; g_Aq2[idx] = pk2; }
    else     { g_Bq1[idx] = pk1; g_Bq2[idx] = pk2; }
    if (lane == 0) { if (isA) g_sA[rloc] = s; else g_sB[rloc] = s; }
}

// ---------------------------------------------------------------------------
// GEMM (Round-9 verbatim): 128x64 tile/CTA, 2 CTAs/SM, grid (128 n, 32 m).
// 256 threads, 8 warps = 4 row-bands x 2 col-bands (warp tile 32x32).
// K=512 in 4 chunks of 128 int8 (SW128).  2-stage cp.async.
// ---------------------------------------------------------------------------
#define AQ1_OFF 0
#define AQ2_OFF 16384
#define BQ1_OFF 32768
#define BQ2_OFF 40960
#define STAGE_BYTES 49152
#define GEMM_SMEM (2 * STAGE_BYTES)

__device__ __forceinline__ void issue_copies(uint32_t sb, int m0, int n0, int ck, int tid) {
    const char* sA1 = (const char*)g_Aq1;
    const char* sA2 = (const char*)g_Aq2;
    const char* sB1 = (const char*)g_Bq1;
    const char* sB2 = (const char*)g_Bq2;
    #pragma unroll
    for (int i = 0; i < 4; i++) {
        int u = tid + 256 * i, r = u >> 3, c = u & 7;
        uint32_t d = sb + AQ1_OFF + (uint32_t)(r * 128 + ((c ^ (r & 7)) * 16));
        CP_ASYNC16(d, sA1 + (size_t)(m0 + r) * 512 + ck * 128 + c * 16);
    }
    #pragma unroll
    for (int i = 0; i < 4; i++) {
        int u = tid + 256 * i, r = u >> 3, c = u & 7;
        uint32_t d = sb + AQ2_OFF + (uint32_t)(r * 128 + ((c ^ (r & 7)) * 16));
        CP_ASYNC16(d, sA2 + (size_t)(m0 + r) * 512 + ck * 128 + c * 16);
    }
    #pragma unroll
    for (int i = 0; i < 2; i++) {
        int u = tid + 256 * i, r = u >> 3, c = u & 7;
        uint32_t d = sb + BQ1_OFF + (uint32_t)(r * 128 + ((c ^ (r & 7)) * 16));
        CP_ASYNC16(d, sB1 + (size_t)(n0 + r) * 512 + ck * 128 + c * 16);
    }
    #pragma unroll
    for (int i = 0; i < 2; i++) {
        int u = tid + 256 * i, r = u >> 3, c = u & 7;
        uint32_t d = sb + BQ2_OFF + (uint32_t)(r * 128 + ((c ^ (r & 7)) * 16));
        CP_ASYNC16(d, sB2 + (size_t)(n0 + r) * 512 + ck * 128 + c * 16);
    }
}

__global__ void __launch_bounds__(256, 2)
gemm_kernel() {
    extern __shared__ __align__(1024) char dyn[];
    uint32_t base = smem_u32(dyn);

    int tid = threadIdx.x;
    int w = tid >> 5, lane = tid & 31;
    int wm = w >> 1, wn = w & 1;
    int q = lane >> 2, t4 = lane & 3;
    int m0 = blockIdx.y * 128, n0 = blockIdx.x * 64;

    int acc1[2][4][4], acc2[2][4][4];
    #pragma unroll
    for (int i = 0; i < 2; i++)
        #pragma unroll
        for (int j = 0; j < 4; j++)
            #pragma unroll
            for (int e = 0; e < 4; e++) { acc1[i][j][e] = 0; acc2[i][j][e] = 0; }

    issue_copies(base + 0 * STAGE_BYTES, m0, n0, 0, tid);
    CP_COMMIT();
    issue_copies(base + 1 * STAGE_BYTES, m0, n0, 1, tid);
    CP_COMMIT();

    int aRow = wm * 32 + ((lane >> 3) & 1) * 8 + (lane & 7);
    int aUsel = lane >> 4;
    int bRow = wn * 32 + lane;

    for (int ck = 0; ck < 4; ck++) {
        uint32_t sb = base + (uint32_t)(ck & 1) * STAGE_BYTES;
        if (ck < 3) { CP_WAIT1(); } else { CP_WAIT0(); }
        __syncthreads();

        #pragma unroll
        for (int ks = 0; ks < 4; ks++) {
            int ub = ks * 2;
            uint32_t a1f[2][4], a2f[2][4];
            #pragma unroll
            for (int mi = 0; mi < 2; mi++) {
                int row = aRow + mi * 16;
                uint32_t su = (uint32_t)((ub + aUsel) ^ (row & 7)) * 16;
                uint32_t ad = sb + (uint32_t)(row * 128) + su;
                LDSM_X4(a1f[mi][0], a1f[mi][1], a1f[mi][2], a1f[mi][3], ad + AQ1_OFF);
                LDSM_X4(a2f[mi][0], a2f[mi][1], a2f[mi][2], a2f[mi][3], ad + AQ2_OFF);
            }
            uint32_t b1u0[4], b1u1[4], b2u0[4], b2u1[4];
            {
                uint32_t su0 = (uint32_t)(ub ^ (lane & 7)) * 16;
                uint32_t su1 = (uint32_t)((ub + 1) ^ (lane & 7)) * 16;
                uint32_t bd = sb + (uint32_t)(bRow * 128);
                LDSM_X4(b1u0[0], b1u0[1], b1u0[2], b1u0[3], bd + BQ1_OFF + su0);
                LDSM_X4(b1u1[0], b1u1[1], b1u1[2], b1u1[3], bd + BQ1_OFF + su1);
                LDSM_X4(b2u0[0], b2u0[1], b2u0[2], b2u0[3], bd + BQ2_OFF + su0);
                LDSM_X4(b2u1[0], b2u1[1], b2u1[2], b2u1[3], bd + BQ2_OFF + su1);
            }
            #pragma unroll
            for (int mi = 0; mi < 2; mi++)
                #pragma unroll
                for (int j = 0; j < 4; j++) {
                    MMA_S8(acc1[mi][j], a1f[mi], b1u0[j], b1u1[j]);
                    MMA_S8(acc2[mi][j], a1f[mi], b2u0[j], b2u1[j]);
                    MMA_S8(acc2[mi][j], a2f[mi], b1u0[j], b1u1[j]);
                }
        }
        __syncthreads();
        if (ck + 2 < 4) {
            issue_copies(sb, m0, n0, ck + 2, tid);
            CP_COMMIT();
        }
    }

    // ---------------- fused epilogue (scales + max reductions) ----------------
    const float inv254 = 1.f / 254.f;
    float sAv[2][2];
    #pragma unroll
    for (int mi = 0; mi < 2; mi++)
        #pragma unroll
        for (int rh = 0; rh < 2; rh++)
            sAv[mi][rh] = g_sA[m0 + wm * 32 + mi * 16 + q + rh * 8];
    float sBv[4][2];
    #pragma unroll
    for (int j = 0; j < 4; j++)
        #pragma unroll
        for (int cp = 0; cp < 2; cp++)
            sBv[j][cp] = g_sB[n0 + wn * 32 + j * 8 + t4 * 2 + cp];

    float sc[2][4][4];
    #pragma unroll
    for (int mi = 0; mi < 2; mi++)
        #pragma unroll
        for (int j = 0; j < 4; j++)
            #pragma unroll
            for (int e = 0; e < 4; e++) {
                float v = __int2float_rn(acc1[mi][j][e]) + __int2float_rn(acc2[mi][j][e]) * inv254;
                sc[mi][j][e] = sAv[mi][e >> 1] * sBv[j][e & 1] * v;
            }

    float* rowred = (float*)dyn;          // [128 rows][2 wn]
    float* colred = (float*)dyn + 256;    // [64 cols][4 a]

    #pragma unroll
    for (int mi = 0; mi < 2; mi++) {
        #pragma unroll
        for (int rh = 0; rh < 2; rh++) {
            float m = fmaxf(sc[mi][0][rh * 2], sc[mi][0][rh * 2 + 1]);
            #pragma unroll
            for (int j = 1; j < 4; j++)
                m = fmaxf(m, fmaxf(sc[mi][j][rh * 2], sc[mi][j][rh * 2 + 1]));
            m = fmaxf(m, __shfl_xor_sync(0xffffffffu, m, 1));
            m = fmaxf(m, __shfl_xor_sync(0xffffffffu, m, 2));
            if (t4 == 0) rowred[(wm * 32 + mi * 16 + q + rh * 8) * 2 + wn] = m;
        }
    }
    #pragma unroll
    for (int j = 0; j < 4; j++) {
        #pragma unroll
        for (int cp = 0; cp < 2; cp++) {
            float m = fmaxf(fmaxf(sc[0][j][cp], sc[0][j][cp + 2]),
                            fmaxf(sc[1][j][cp], sc[1][j][cp + 2]));
            m = fmaxf(m, __shfl_xor_sync(0xffffffffu, m, 4));
            m = fmaxf(m, __shfl_xor_sync(0xffffffffu, m, 8));
            m = fmaxf(m, __shfl_xor_sync(0xffffffffu, m, 16));
            if (q == 0) colred[(wn * 32 + j * 8 + t4 * 2 + cp) * 4 + wm] = m;
        }
    }
    __syncthreads();

    if (w < 4) {
        int a = w;
        int aG = blockIdx.y * 4 + a;
        int bG = blockIdx.x;
        float rf = fmaxf(rowred[(a * 32 + lane) * 2 + 0],
                         rowred[(a * 32 + lane) * 2 + 1]);
        float val = rf * g_wA[aG * 32 + lane];
        val += colred[lane * 4 + a]        * g_wB[bG * 64 + lane];
        val += colred[(lane + 32) * 4 + a] * g_wB[bG * 64 + lane + 32];
        #pragma unroll
        for (int o = 16; o; o >>= 1) val += __shfl_xor_sync(0xffffffffu, val, o);
        if (lane == 0) g_score[aG * 128 + bG] = 0.5f * val;
    }
}

// ---------------------------------------------------------------------------
// loss: 1024 threads, smem-staged.  Each thread owns a 32-elem strip of one
// (side,row) pair; 4-strip groups combine max then sum via smem.
// ---------------------------------------------------------------------------
#define LOSS_SMEM (16384 * 4 + 2048 * 4 + 256 * 4)
__global__ void __launch_bounds__(1024)
loss_kernel(const float* __restrict__ temp, float* __restrict__ out) {
    extern __shared__ __align__(16) float ls[];
    float* aux  = ls + 16384;        // [1024] strip maxes
    float* aux2 = aux + 1024;        // [1024] strip sums
    float* red  = aux2 + 1024;       // [256] per-(side,i) losses
    int tid = threadIdx.x;
    float invT = 1.0f / temp[0];

    float4* d4 = (float4*)ls;
    const float4* s4 = (const float4*)g_score;
    for (int i = tid; i < 4096; i += 1024) d4[i] = s4[i];
    __syncthreads();

    int side = tid >> 9;             // 0 = rows, 1 = cols
    int i = (tid >> 2) & 127;
    int st = tid & 3;

    float mx = NEG_BIG;
    #pragma unroll 8
    for (int j = 0; j < 32; j++) {
        float x = side ? ls[(st * 32 + j) * 128 + i] : ls[i * 128 + st * 32 + j];
        mx = fmaxf(mx, x);
    }
    aux[tid] = mx;
    __syncthreads();
    int gb = tid & ~3;
    float gmx = fmaxf(fmaxf(aux[gb], aux[gb + 1]), fmaxf(aux[gb + 2], aux[gb + 3]));

    float s = 0.f;
    #pragma unroll 8
    for (int j = 0; j < 32; j++) {
        float x = side ? ls[(st * 32 + j) * 128 + i] : ls[i * 128 + st * 32 + j];
        s += expf((x - gmx) * invT);
    }
    aux2[tid] = s;
    __syncthreads();
    if (st == 0) {
        float gs = aux2[gb] + aux2[gb + 1] + aux2[gb + 2] + aux2[gb + 3];
        float lse = gmx * invT + logf(gs);
        red[side * 128 + i] = lse - ls[i * 128 + i] * invT;
    }
    __syncthreads();
    for (int o = 128; o; o >>= 1) {
        if (tid < o) red[tid] += red[tid + o];
        __syncthreads();
    }
    if (tid == 0) out[0] = red[0] / 256.f;
}

// ---------------------------------------------------------------------------
extern "C" void kernel_launch(void* const* d_in, const int* in_sizes, int n_in,
                              void* d_out, int out_size) {
    (void)out_size;
    int order[7];
    for (int i = 0; i < 7 && i < n_in; i++) order[i] = i;
    for (int i = 1; i < 7; i++) {
        int o = order[i];
        long long s = in_sizes[o];
        int j = i - 1;
        while (j >= 0 && (long long)in_sizes[order[j]] > s) { order[j + 1] = order[j]; j--; }
        order[j + 1] = o;
    }
    const float* temp  = (const float*)d_in[order[0]];
    const void*  q0    = d_in[order[1]];
    const void*  q1    = d_in[order[2]];
    const void*  r0    = d_in[order[3]];
    const void*  r1    = d_in[order[4]];
    const float* featA = (const float*)d_in[order[5]];
    const float* featB = (const float*)d_in[order[6]];
    float* out = (float*)d_out;

    static bool attrSet = false;
    if (!attrSet) {
        cudaFuncSetAttribute(gemm_kernel, cudaFuncAttributeMaxDynamicSharedMemorySize, GEMM_SMEM);
        cudaFuncSetAttribute(loss_kernel, cudaFuncAttributeMaxDynamicSharedMemorySize, LOSS_SMEM);
        attrSet = true;
    }

    quant_prep_kernel<<<1664, 256>>>(featA, featB, q0, q1, r0, r1);
    gemm_kernel<<<dim3(128, 32), 256, GEMM_SMEM>>>();
    loss_kernel<<<1, 1024, LOSS_SMEM>>>(temp, out);
}

// round 13
// speedup vs baseline: 1.0682x; 1.0014x over previous
#include <cuda_runtime.h>
#include <math.h>
#include <stdint.h>

// ---------------------------------------------------------------------------
// B=128, T=32, V=64, D=512.  score[128][128].
// sm_100 BASELINE target: mma.sync s8 (m16n8k32) + cp.async + ldmatrix.
// 2-level int8 row-scaled split:  x = s*(q1 + q2/254) + O(s/508)
//   score = sA[r]*sB[c]*( Σq1a*q1b + (Σq1a*q2b + Σq2a*q1b)/254 )
//   quant_prep:  per-row amax+quantize (prmt-packed, clamp-free) + scales;
//                masked-softmax weights
//   gemm_kernel: 128x64 tile/CTA (grid 128x32), 2 CTAs/SM, 2-stage cp.async,
//                dependency-depth-ordered inner loop, fused scale+max epilogue
//   loss_kernel: 1024-thread smem-staged log-softmax -> scalar
// ---------------------------------------------------------------------------

#define NEG_BIG (-3.0e38f)

__device__ float g_wA[128 * 32];
__device__ float g_wB[128 * 64];
__device__ float g_score[128 * 128];
__device__ float g_sA[4096];
__device__ float g_sB[8192];

__device__ uint4 g_Aq1[4096 * 512 / 16];
__device__ uint4 g_Aq2[4096 * 512 / 16];
__device__ uint4 g_Bq1[8192 * 512 / 16];
__device__ uint4 g_Bq2[8192 * 512 / 16];

// ---------------- PTX helpers ----------------
__device__ __forceinline__ uint32_t smem_u32(const void* p) {
    uint32_t a;
    asm("{ .reg .u64 t; cvta.to.shared.u64 t, %1; cvt.u32.u64 %0, t; }" : "=r"(a) : "l"(p));
    return a;
}
__device__ __forceinline__ uint32_t prmt(uint32_t a, uint32_t b, uint32_t s) {
    uint32_t r;
    asm("prmt.b32 %0, %1, %2, %3;" : "=r"(r) : "r"(a), "r"(b), "r"(s));
    return r;
}
#define CP_ASYNC16(dst, src) asm volatile("cp.async.cg.shared.global [%0], [%1], 16;" :: "r"(dst), "l"(src))
#define CP_COMMIT()          asm volatile("cp.async.commit_group;" ::: "memory")
#define CP_WAIT1()           asm volatile("cp.async.wait_group 1;" ::: "memory")
#define CP_WAIT0()           asm volatile("cp.async.wait_group 0;" ::: "memory")
#define LDSM_X4(r0, r1, r2, r3, addr) \
    asm volatile("ldmatrix.sync.aligned.m8n8.x4.shared.b16 {%0,%1,%2,%3}, [%4];" \
        : "=r"(r0), "=r"(r1), "=r"(r2), "=r"(r3) : "r"(addr))
#define MMA_S8(d, a, b0, b1) \
    asm volatile("mma.sync.aligned.m16n8k32.row.col.s32.s8.s8.s32 " \
        "{%0,%1,%2,%3}, {%4,%5,%6,%7}, {%8,%9}, {%0,%1,%2,%3};" \
        : "+r"((d)[0]), "+r"((d)[1]), "+r"((d)[2]), "+r"((d)[3]) \
        : "r"((a)[0]), "r"((a)[1]), "r"((a)[2]), "r"((a)[3]), "r"(b0), "r"(b1))

// ---------------- input disambiguation ----------------
__device__ __forceinline__ bool looks_like_int_small(const unsigned* w, unsigned limit) {
    bool ok = true;
    #pragma unroll
    for (int i = 0; i < 8; i++) ok = ok && (w[i] <= limit);
    return ok;
}
__device__ __forceinline__ bool int_width64(const unsigned* w) {
    return (w[1] == 0u) && (w[3] == 0u) && (w[5] == 0u) && (w[7] == 0u);
}
__device__ __forceinline__ bool int_elem_nonzero(const unsigned* w, int i, bool w64) {
    return w64 ? ((w[2 * i] | w[2 * i + 1]) != 0u) : (w[i] != 0u);
}

// ---------------------------------------------------------------------------
// quant + prep.  Blocks [0,1536): one warp per feature row (12288 rows).
// Blocks [1536,1664): masked-softmax weights.
// ---------------------------------------------------------------------------
__global__ void __launch_bounds__(256)
quant_prep_kernel(const float* __restrict__ A, const float* __restrict__ B,
                  const void* q0, const void* q1p, const void* r0, const void* r1) {
    bool q0_tok = looks_like_int_small((const unsigned*)q0, 99999u);
    const unsigned* tokw = (const unsigned*)(q0_tok ? q0 : q1p);
    const float*    wtA  = (const float*)(q0_tok ? q1p : q0);
    bool tok64 = int_width64(tokw);
    bool r0_msk = looks_like_int_small((const unsigned*)r0, 1u);
    const unsigned* mskw = (const unsigned*)(r0_msk ? r0 : r1);
    const float*    wtB  = (const float*)(r0_msk ? r1 : r0);
    bool msk64 = int_width64(mskw);

    if (blockIdx.x >= 1536) {
        int row = blockIdx.x - 1536;
        int w = threadIdx.x >> 5, lane = threadIdx.x & 31;
        if (w == 0) {
            float m = int_elem_nonzero(tokw, row * 32 + lane, tok64) ? 1.f : 0.f;
            float x = (m > 0.f) ? wtA[row * 32 + lane] : NEG_BIG;
            float mx = x;
            #pragma unroll
            for (int o = 16; o; o >>= 1) mx = fmaxf(mx, __shfl_xor_sync(0xffffffffu, mx, o));
            float e = expf(x - mx), s = e;
            #pragma unroll
            for (int o = 16; o; o >>= 1) s += __shfl_xor_sync(0xffffffffu, s, o);
            g_wA[row * 32 + lane] = e / s;
        } else if (w == 1) {
            float m0 = int_elem_nonzero(mskw, row * 64 + lane, msk64) ? 1.f : 0.f;
            float m1 = int_elem_nonzero(mskw, row * 64 + lane + 32, msk64) ? 1.f : 0.f;
            float x0 = (m0 > 0.f) ? wtB[row * 64 + lane] : NEG_BIG;
            float x1 = (m1 > 0.f) ? wtB[row * 64 + lane + 32] : NEG_BIG;
            float mx = fmaxf(x0, x1);
            #pragma unroll
            for (int o = 16; o; o >>= 1) mx = fmaxf(mx, __shfl_xor_sync(0xffffffffu, mx, o));
            float e0 = expf(x0 - mx), e1 = expf(x1 - mx);
            float s = e0 + e1;
            #pragma unroll
            for (int o = 16; o; o >>= 1) s += __shfl_xor_sync(0xffffffffu, s, o);
            g_wB[row * 64 + lane] = e0 / s;
            g_wB[row * 64 + lane + 32] = e1 / s;
        }
        return;
    }

    int w = threadIdx.x >> 5, lane = threadIdx.x & 31;
    int row = blockIdx.x * 8 + w;
    bool isA = row < 4096;
    int rloc = isA ? row : row - 4096;
    const float* src = isA ? (A + (size_t)rloc * 512) : (B + (size_t)rloc * 512);
    float m = isA ? (int_elem_nonzero(tokw, rloc, tok64) ? 1.f : 0.f)
                  : (int_elem_nonzero(mskw, rloc, msk64) ? 1.f : 0.f);

    float v[16];
    #pragma unroll
    for (int i = 0; i < 4; i++) {
        float4 x = ((const float4*)src)[lane * 4 + i];
        v[i * 4 + 0] = x.x * m;
        v[i * 4 + 1] = x.y * m;
        v[i * 4 + 2] = x.z * m;
        v[i * 4 + 3] = x.w * m;
    }
    float amax = 0.f;
    #pragma unroll
    for (int i = 0; i < 16; i++) amax = fmaxf(amax, fabsf(v[i]));
    #pragma unroll
    for (int o = 16; o; o >>= 1) amax = fmaxf(amax, __shfl_xor_sync(0xffffffffu, amax, o));

    float sInv = (amax > 0.f) ? (127.f / amax) : 0.f;
    float s = amax * (1.f / 127.f);

    // clamp-free: |x| <= amax  =>  |rint(x*sInv)| <= 127 exactly;
    // |r| <= s/2  =>  |rint(r*254*sInv)| <= 127.
    uint32_t p1[4], p2[4];
    #pragma unroll
    for (int g = 0; g < 4; g++) {
        uint32_t i1v[4], i2v[4];
        #pragma unroll
        for (int k = 0; k < 4; k++) {
            float x = v[g * 4 + k];
            float f1 = rintf(x * sInv);
            float r = fmaf(-f1, s, x);
            float f2 = rintf(r * 254.f * sInv);
            i1v[k] = (uint32_t)(int)f1;
            i2v[k] = (uint32_t)(int)f2;
        }
        p1[g] = prmt(prmt(i1v[0], i1v[1], 0x0040u), prmt(i1v[2], i1v[3], 0x0040u), 0x5410u);
        p2[g] = prmt(prmt(i2v[0], i2v[1], 0x0040u), prmt(i2v[2], i2v[3], 0x0040u), 0x5410u);
    }
    uint4 pk1 = make_uint4(p1[0], p1[1], p1[2], p1[3]);
    uint4 pk2 = make_uint4(p2[0], p2[1], p2[2], p2[3]);
    size_t idx = (size_t)rloc * 32 + lane;
    if (isA) { g_Aq1[idx] = pk1; g_Aq2[idx] = pk2; }
    else     { g_Bq1[idx] = pk1; g_Bq2[idx] = pk2; }
    if (lane == 0) { if (isA) g_sA[rloc] = s; else g_sB[rloc] = s; }
}

// ---------------------------------------------------------------------------
// GEMM: 128x64 tile/CTA, 2 CTAs/SM, grid (128 n, 32 m).  256 threads,
// 8 warps = 4 row-bands x 2 col-bands (warp tile 32x32).  K=512 in 4 chunks
// of 128 int8 (SW128).  2-stage cp.async.  Inner loop ordered by dependency
// depth: LDSM a1,b1,b2,a2 -> MMA acc1 -> MMA acc2(a1b2) -> MMA acc2(a2b1).
// ---------------------------------------------------------------------------
#define AQ1_OFF 0
#define AQ2_OFF 16384
#define BQ1_OFF 32768
#define BQ2_OFF 40960
#define STAGE_BYTES 49152
#define GEMM_SMEM (2 * STAGE_BYTES)

__device__ __forceinline__ void issue_copies(uint32_t sb, int m0, int n0, int ck, int tid) {
    const char* sA1 = (const char*)g_Aq1;
    const char* sA2 = (const char*)g_Aq2;
    const char* sB1 = (const char*)g_Bq1;
    const char* sB2 = (const char*)g_Bq2;
    #pragma unroll
    for (int i = 0; i < 4; i++) {
        int u = tid + 256 * i, r = u >> 3, c = u & 7;
        uint32_t d = sb + AQ1_OFF + (uint32_t)(r * 128 + ((c ^ (r & 7)) * 16));
        CP_ASYNC16(d, sA1 + (size_t)(m0 + r) * 512 + ck * 128 + c * 16);
    }
    #pragma unroll
    for (int i = 0; i < 4; i++) {
        int u = tid + 256 * i, r = u >> 3, c = u & 7;
        uint32_t d = sb + AQ2_OFF + (uint32_t)(r * 128 + ((c ^ (r & 7)) * 16));
        CP_ASYNC16(d, sA2 + (size_t)(m0 + r) * 512 + ck * 128 + c * 16);
    }
    #pragma unroll
    for (int i = 0; i < 2; i++) {
        int u = tid + 256 * i, r = u >> 3, c = u & 7;
        uint32_t d = sb + BQ1_OFF + (uint32_t)(r * 128 + ((c ^ (r & 7)) * 16));
        CP_ASYNC16(d, sB1 + (size_t)(n0 + r) * 512 + ck * 128 + c * 16);
    }
    #pragma unroll
    for (int i = 0; i < 2; i++) {
        int u = tid + 256 * i, r = u >> 3, c = u & 7;
        uint32_t d = sb + BQ2_OFF + (uint32_t)(r * 128 + ((c ^ (r & 7)) * 16));
        CP_ASYNC16(d, sB2 + (size_t)(n0 + r) * 512 + ck * 128 + c * 16);
    }
}

__global__ void __launch_bounds__(256, 2)
gemm_kernel() {
    extern __shared__ __align__(1024) char dyn[];
    uint32_t base = smem_u32(dyn);

    int tid = threadIdx.x;
    int w = tid >> 5, lane = tid & 31;
    int wm = w >> 1, wn = w & 1;
    int q = lane >> 2, t4 = lane & 3;
    int m0 = blockIdx.y * 128, n0 = blockIdx.x * 64;

    int acc1[2][4][4], acc2[2][4][4];
    #pragma unroll
    for (int i = 0; i < 2; i++)
        #pragma unroll
        for (int j = 0; j < 4; j++)
            #pragma unroll
            for (int e = 0; e < 4; e++) { acc1[i][j][e] = 0; acc2[i][j][e] = 0; }

    issue_copies(base + 0 * STAGE_BYTES, m0, n0, 0, tid);
    CP_COMMIT();
    issue_copies(base + 1 * STAGE_BYTES, m0, n0, 1, tid);
    CP_COMMIT();

    int aRow = wm * 32 + ((lane >> 3) & 1) * 8 + (lane & 7);
    int aUsel = lane >> 4;
    int bRow = wn * 32 + lane;

    for (int ck = 0; ck < 4; ck++) {
        uint32_t sb = base + (uint32_t)(ck & 1) * STAGE_BYTES;
        if (ck < 3) { CP_WAIT1(); } else { CP_WAIT0(); }
        __syncthreads();

        #pragma unroll
        for (int ks = 0; ks < 4; ks++) {
            int ub = ks * 2;
            uint32_t a1f[2][4], a2f[2][4];
            uint32_t b1u0[4], b1u1[4], b2u0[4], b2u1[4];
            uint32_t su0 = (uint32_t)(ub ^ (lane & 7)) * 16;
            uint32_t su1 = (uint32_t)((ub + 1) ^ (lane & 7)) * 16;
            uint32_t bd = sb + (uint32_t)(bRow * 128);
            uint32_t suA0 = (uint32_t)((ub + aUsel) ^ (aRow & 7)) * 16;
            uint32_t suA1 = (uint32_t)((ub + aUsel) ^ ((aRow + 16) & 7)) * 16;
            uint32_t ad0 = sb + (uint32_t)(aRow * 128) + suA0;
            uint32_t ad1 = sb + (uint32_t)((aRow + 16) * 128) + suA1;

            // depth-ordered LDSM: inputs of acc1 first, a2 (deepest consumer) last
            LDSM_X4(a1f[0][0], a1f[0][1], a1f[0][2], a1f[0][3], ad0 + AQ1_OFF);
            LDSM_X4(a1f[1][0], a1f[1][1], a1f[1][2], a1f[1][3], ad1 + AQ1_OFF);
            LDSM_X4(b1u0[0], b1u0[1], b1u0[2], b1u0[3], bd + BQ1_OFF + su0);
            LDSM_X4(b1u1[0], b1u1[1], b1u1[2], b1u1[3], bd + BQ1_OFF + su1);
            LDSM_X4(b2u0[0], b2u0[1], b2u0[2], b2u0[3], bd + BQ2_OFF + su0);
            LDSM_X4(b2u1[0], b2u1[1], b2u1[2], b2u1[3], bd + BQ2_OFF + su1);
            LDSM_X4(a2f[0][0], a2f[0][1], a2f[0][2], a2f[0][3], ad0 + AQ2_OFF);
            LDSM_X4(a2f[1][0], a2f[1][1], a2f[1][2], a2f[1][3], ad1 + AQ2_OFF);

            // bank 1: a1*b1 (ready after first 4 LDSMs; covers tail LDSM latency)
            #pragma unroll
            for (int mi = 0; mi < 2; mi++)
                #pragma unroll
                for (int j = 0; j < 4; j++)
                    MMA_S8(acc1[mi][j], a1f[mi], b1u0[j], b1u1[j]);
            // bank 2a: a1*b2
            #pragma unroll
            for (int mi = 0; mi < 2; mi++)
                #pragma unroll
                for (int j = 0; j < 4; j++)
                    MMA_S8(acc2[mi][j], a1f[mi], b2u0[j], b2u1[j]);
            // bank 2b: a2*b1
            #pragma unroll
            for (int mi = 0; mi < 2; mi++)
                #pragma unroll
                for (int j = 0; j < 4; j++)
                    MMA_S8(acc2[mi][j], a2f[mi], b1u0[j], b1u1[j]);
        }
        __syncthreads();
        if (ck + 2 < 4) {
            issue_copies(sb, m0, n0, ck + 2, tid);
            CP_COMMIT();
        }
    }

    // ---------------- fused epilogue (scales + max reductions) ----------------
    const float inv254 = 1.f / 254.f;
    float sAv[2][2];
    #pragma unroll
    for (int mi = 0; mi < 2; mi++)
        #pragma unroll
        for (int rh = 0; rh < 2; rh++)
            sAv[mi][rh] = g_sA[m0 + wm * 32 + mi * 16 + q + rh * 8];
    float sBv[4][2];
    #pragma unroll
    for (int j = 0; j < 4; j++)
        #pragma unroll
        for (int cp = 0; cp < 2; cp++)
            sBv[j][cp] = g_sB[n0 + wn * 32 + j * 8 + t4 * 2 + cp];

    float sc[2][4][4];
    #pragma unroll
    for (int mi = 0; mi < 2; mi++)
        #pragma unroll
        for (int j = 0; j < 4; j++)
            #pragma unroll
            for (int e = 0; e < 4; e++) {
                float v = __int2float_rn(acc1[mi][j][e]) + __int2float_rn(acc2[mi][j][e]) * inv254;
                sc[mi][j][e] = sAv[mi][e >> 1] * sBv[j][e & 1] * v;
            }

    float* rowred = (float*)dyn;          // [128 rows][2 wn]
    float* colred = (float*)dyn + 256;    // [64 cols][4 a]

    #pragma unroll
    for (int mi = 0; mi < 2; mi++) {
        #pragma unroll
        for (int rh = 0; rh < 2; rh++) {
            float m = fmaxf(sc[mi][0][rh * 2], sc[mi][0][rh * 2 + 1]);
            #pragma unroll
            for (int j = 1; j < 4; j++)
                m = fmaxf(m, fmaxf(sc[mi][j][rh * 2], sc[mi][j][rh * 2 + 1]));
            m = fmaxf(m, __shfl_xor_sync(0xffffffffu, m, 1));
            m = fmaxf(m, __shfl_xor_sync(0xffffffffu, m, 2));
            if (t4 == 0) rowred[(wm * 32 + mi * 16 + q + rh * 8) * 2 + wn] = m;
        }
    }
    #pragma unroll
    for (int j = 0; j < 4; j++) {
        #pragma unroll
        for (int cp = 0; cp < 2; cp++) {
            float m = fmaxf(fmaxf(sc[0][j][cp], sc[0][j][cp + 2]),
                            fmaxf(sc[1][j][cp], sc[1][j][cp + 2]));
            m = fmaxf(m, __shfl_xor_sync(0xffffffffu, m, 4));
            m = fmaxf(m, __shfl_xor_sync(0xffffffffu, m, 8));
            m = fmaxf(m, __shfl_xor_sync(0xffffffffu, m, 16));
            if (q == 0) colred[(wn * 32 + j * 8 + t4 * 2 + cp) * 4 + wm] = m;
        }
    }
    __syncthreads();

    if (w < 4) {
        int a = w;
        int aG = blockIdx.y * 4 + a;
        int bG = blockIdx.x;
        float rf = fmaxf(rowred[(a * 32 + lane) * 2 + 0],
                         rowred[(a * 32 + lane) * 2 + 1]);
        float val = rf * g_wA[aG * 32 + lane];
        val += colred[lane * 4 + a]        * g_wB[bG * 64 + lane];
        val += colred[(lane + 32) * 4 + a] * g_wB[bG * 64 + lane + 32];
        #pragma unroll
        for (int o = 16; o; o >>= 1) val += __shfl_xor_sync(0xffffffffu, val, o);
        if (lane == 0) g_score[aG * 128 + bG] = 0.5f * val;
    }
}

// ---------------------------------------------------------------------------
// loss: 1024 threads, smem-staged, strip-parallel.
// ---------------------------------------------------------------------------
#define LOSS_SMEM (16384 * 4 + 2048 * 4 + 256 * 4)
__global__ void __launch_bounds__(1024)
loss_kernel(const float* __restrict__ temp, float* __restrict__ out) {
    extern __shared__ __align__(16) float ls[];
    float* aux  = ls + 16384;
    float* aux2 = aux + 1024;
    float* red  = aux2 + 1024;
    int tid = threadIdx.x;
    float invT = 1.0f / temp[0];

    float4* d4 = (float4*)ls;
    const float4* s4 = (const float4*)g_score;
    for (int i = tid; i < 4096; i += 1024) d4[i] = s4[i];
    __syncthreads();

    int side = tid >> 9;
    int i = (tid >> 2) & 127;
    int st = tid & 3;

    float mx = NEG_BIG;
    #pragma unroll 8
    for (int j = 0; j < 32; j++) {
        float x = side ? ls[(st * 32 + j) * 128 + i] : ls[i * 128 + st * 32 + j];
        mx = fmaxf(mx, x);
    }
    aux[tid] = mx;
    __syncthreads();
    int gb = tid & ~3;
    float gmx = fmaxf(fmaxf(aux[gb], aux[gb + 1]), fmaxf(aux[gb + 2], aux[gb + 3]));

    float s = 0.f;
    #pragma unroll 8
    for (int j = 0; j < 32; j++) {
        float x = side ? ls[(st * 32 + j) * 128 + i] : ls[i * 128 + st * 32 + j];
        s += expf((x - gmx) * invT);
    }
    aux2[tid] = s;
    __syncthreads();
    if (st == 0) {
        float gs = aux2[gb] + aux2[gb + 1] + aux2[gb + 2] + aux2[gb + 3];
        float lse = gmx * invT + logf(gs);
        red[side * 128 + i] = lse - ls[i * 128 + i] * invT;
    }
    __syncthreads();
    for (int o = 128; o; o >>= 1) {
        if (tid < o) red[tid] += red[tid + o];
        __syncthreads();
    }
    if (tid == 0) out[0] = red[0] / 256.f;
}

// ---------------------------------------------------------------------------
extern "C" void kernel_launch(void* const* d_in, const int* in_sizes, int n_in,
                              void* d_out, int out_size) {
    (void)out_size;
    int order[7];
    for (int i = 0; i < 7 && i < n_in; i++) order[i] = i;
    for (int i = 1; i < 7; i++) {
        int o = order[i];
        long long s = in_sizes[o];
        int j = i - 1;
        while (j >= 0 && (long long)in_sizes[order[j]] > s) { order[j + 1] = order[j]; j--; }
        order[j + 1] = o;
    }
    const float* temp  = (const float*)d_in[order[0]];
    const void*  q0    = d_in[order[1]];
    const void*  q1    = d_in[order[2]];
    const void*  r0    = d_in[order[3]];
    const void*  r1    = d_in[order[4]];
    const float* featA = (const float*)d_in[order[5]];
    const float* featB = (const float*)d_in[order[6]];
    float* out = (float*)d_out;

    static bool attrSet = false;
    if (!attrSet) {
        cudaFuncSetAttribute(gemm_kernel, cudaFuncAttributeMaxDynamicSharedMemorySize, GEMM_SMEM);
        cudaFuncSetAttribute(loss_kernel, cudaFuncAttributeMaxDynamicSharedMemorySize, LOSS_SMEM);
        attrSet = true;
    }

    quant_prep_kernel<<<1664, 256>>>(featA, featB, q0, q1, r0, r1);
    gemm_kernel<<<dim3(128, 32), 256, GEMM_SMEM>>>();
    loss_kernel<<<1, 1024, LOSS_SMEM>>>(temp, out);
}